// round 1
// baseline (speedup 1.0000x reference)
#include <cuda_runtime.h>
#include <math.h>

// SSIM loss, fully fused: separable 11x11 Gaussian, 5 moment maps, epilogue,
// global mean, all in one main kernel + tiny zero/finalize kernels.
//
// Shapes: im1, im2: (32,3,512,512) fp32; window: (3,1,11,11) fp32 (outer(g,g));
// output: scalar fp32 = -mean(ssim_map).

#define TX    32
#define TY    32
#define HALO  5
#define RX    (TX + 2*HALO)   // 42
#define RY    (TY + 2*HALO)   // 42
#define IMG_H 512
#define IMG_W 512
#define NPLANES 96            // 32*3
#define NPIX  25165824.0      // 32*3*512*512

__device__ double g_accum;

__global__ void ssim_zero_kernel() { g_accum = 0.0; }

__global__ void __launch_bounds__(256, 4)
ssim_main_kernel(const float* __restrict__ im1,
                 const float* __restrict__ im2,
                 const float* __restrict__ window)
{
    __shared__ float s1[RY][RX + 2];
    __shared__ float s2[RY][RX + 2];
    __shared__ float hb[5][RY][TX];     // horizontal-pass moment bands
    __shared__ float gw[11];
    __shared__ float warpsum[8];

    const int tid = threadIdx.y * 32 + threadIdx.x;   // block = 32x8

    // Recover 1-D Gaussian from the 2-D outer-product window:
    // w2d[5][k] = g[5]*g[k]  ->  g[k] = w2d[5][k] / sqrt(w2d[5][5])
    if (tid < 11) {
        float g5 = sqrtf(window[5 * 11 + 5]);
        gw[tid] = window[5 * 11 + tid] / g5;
    }

    const int x0 = blockIdx.x * TX;
    const int y0 = blockIdx.y * TY;
    const long plane = (long)blockIdx.z * (IMG_H * IMG_W);
    const float* __restrict__ p1 = im1 + plane;
    const float* __restrict__ p2 = im2 + plane;

    // ---- load 42x42 tiles with zero padding (jax conv pads with 0) ----
    for (int idx = tid; idx < RY * RX; idx += 256) {
        int r = idx / RX;
        int c = idx - r * RX;
        int gy = y0 + r - HALO;
        int gx = x0 + c - HALO;
        float v1 = 0.0f, v2 = 0.0f;
        if ((unsigned)gy < (unsigned)IMG_H && (unsigned)gx < (unsigned)IMG_W) {
            int o = gy * IMG_W + gx;
            v1 = p1[o];
            v2 = p2[o];
        }
        s1[r][c] = v1;
        s2[r][c] = v2;
    }
    __syncthreads();

    // ---- horizontal separable pass: 5 moments over 42 rows x 32 cols ----
    for (int idx = tid; idx < RY * TX; idx += 256) {
        int r = idx >> 5;
        int c = idx & 31;
        float a1 = 0.f, a2 = 0.f, a11 = 0.f, a22 = 0.f, a12 = 0.f;
        #pragma unroll
        for (int k = 0; k < 11; k++) {
            float g  = gw[k];
            float v1 = s1[r][c + k];
            float v2 = s2[r][c + k];
            float m1 = g * v1;
            float m2 = g * v2;
            a1  += m1;
            a2  += m2;
            a11 += m1 * v1;
            a22 += m2 * v2;
            a12 += m1 * v2;
        }
        hb[0][r][c] = a1;
        hb[1][r][c] = a2;
        hb[2][r][c] = a11;
        hb[3][r][c] = a22;
        hb[4][r][c] = a12;
    }
    __syncthreads();

    // ---- vertical pass + SSIM epilogue ----
    const float C1 = 1e-4f;   // 0.01^2
    const float C2 = 9e-4f;   // 0.03^2
    float lsum = 0.0f;
    for (int idx = tid; idx < TY * TX; idx += 256) {
        int y = idx >> 5;
        int x = idx & 31;
        float mu1 = 0.f, mu2 = 0.f, e11 = 0.f, e22 = 0.f, e12 = 0.f;
        #pragma unroll
        for (int k = 0; k < 11; k++) {
            float g = gw[k];
            mu1 += g * hb[0][y + k][x];
            mu2 += g * hb[1][y + k][x];
            e11 += g * hb[2][y + k][x];
            e22 += g * hb[3][y + k][x];
            e12 += g * hb[4][y + k][x];
        }
        float m1s = mu1 * mu1;
        float m2s = mu2 * mu2;
        float m12 = mu1 * mu2;
        float v1q = e11 - m1s;
        float v2q = e22 - m2s;
        float v12 = e12 - m12;
        float num = (2.0f * m12 + C1) * (2.0f * v12 + C2);
        float den = (m1s + m2s + C1) * (v1q + v2q + C2);
        lsum += __fdividef(num, den);
    }

    // ---- block reduction ----
    #pragma unroll
    for (int o = 16; o > 0; o >>= 1)
        lsum += __shfl_down_sync(0xffffffffu, lsum, o);
    if (threadIdx.x == 0) warpsum[threadIdx.y] = lsum;
    __syncthreads();
    if (tid == 0) {
        float t = 0.f;
        #pragma unroll
        for (int i = 0; i < 8; i++) t += warpsum[i];
        atomicAdd(&g_accum, (double)t);
    }
}

__global__ void ssim_finalize_kernel(float* out) {
    out[0] = (float)(-g_accum / NPIX);
}

extern "C" void kernel_launch(void* const* d_in, const int* in_sizes, int n_in,
                              void* d_out, int out_size)
{
    const float* im1 = (const float*)d_in[0];
    const float* im2 = (const float*)d_in[1];
    const float* win = (const float*)d_in[2];
    float* out = (float*)d_out;

    ssim_zero_kernel<<<1, 1>>>();
    dim3 grid(IMG_W / TX, IMG_H / TY, NPLANES);
    dim3 block(32, 8);
    ssim_main_kernel<<<grid, block>>>(im1, im2, win);
    ssim_finalize_kernel<<<1, 1>>>(out);
}

// round 2
// speedup vs baseline: 1.4016x; 1.4016x over previous
#include <cuda_runtime.h>
#include <math.h>

// Fused SSIM loss with packed f32x2 math (Blackwell) and register blocking.
// im1, im2: (32,3,512,512) fp32; window: (3,1,11,11) fp32 outer(g,g).
// out: scalar fp32 = -mean(ssim_map).

#define TX 32
#define TY 32
#define HALO 5
#define RX 42
#define RXP 44          // padded pixel stride (multiple of 4 -> 16B-aligned vec loads)
#define RY 42
#define IMG 512
#define NPLANES 96
#define NPIX 25165824.0

typedef unsigned long long u64;

__device__ __forceinline__ u64 pk2(float a, float b) {
    u64 r; asm("mov.b64 %0,{%1,%2};" : "=l"(r) : "f"(a), "f"(b)); return r;
}
__device__ __forceinline__ void unpk(u64 v, float& a, float& b) {
    asm("mov.b64 {%0,%1},%2;" : "=f"(a), "=f"(b) : "l"(v));
}
__device__ __forceinline__ u64 fma2(u64 a, u64 b, u64 c) {
    u64 d; asm("fma.rn.f32x2 %0,%1,%2,%3;" : "=l"(d) : "l"(a), "l"(b), "l"(c)); return d;
}
__device__ __forceinline__ u64 mul2(u64 a, u64 b) {
    u64 d; asm("mul.rn.f32x2 %0,%1,%2;" : "=l"(d) : "l"(a), "l"(b)); return d;
}
__device__ __forceinline__ u64 add2(u64 a, u64 b) {
    u64 d; asm("add.rn.f32x2 %0,%1,%2;" : "=l"(d) : "l"(a), "l"(b)); return d;
}

__device__ double g_accum;

__global__ void ssim_zero_kernel() { g_accum = 0.0; }

__global__ void __launch_bounds__(256, 3)
ssim_main_kernel(const float* __restrict__ im1,
                 const float* __restrict__ im2,
                 const float* __restrict__ window)
{
    __shared__ u64   s12[RY][RXP];     // packed (v1,v2) input tile   14784 B
    __shared__ u64   hbM[RY][TX];      // packed (m1,m2) h-moments    10752 B
    __shared__ u64   hbE[RY][TX];      // packed (e11,e22)            10752 B
    __shared__ float hb12[RY][TX];     // e12 scalar                   5376 B
    __shared__ u64   ggp[11];          // packed (g,g)
    __shared__ float warpsum[8];

    const int tid = threadIdx.x;       // block = 256 flat

    if (tid < 11) {
        float g5 = sqrtf(window[5 * 11 + 5]);
        float g  = window[5 * 11 + tid] / g5;
        ggp[tid] = pk2(g, g);
    }

    const int x0 = blockIdx.x * TX;
    const int y0 = blockIdx.y * TY;
    const long plane = (long)blockIdx.z * (IMG * IMG);
    const float* __restrict__ p1 = im1 + plane;
    const float* __restrict__ p2 = im2 + plane;

    // ---- load 42x42 packed tile with zero padding ----
    #pragma unroll
    for (int i = 0; i < 7; i++) {
        int idx = tid + i * 256;
        if (idx < RY * RX) {
            int r = idx / RX;
            int c = idx - r * RX;
            int gy = y0 + r - HALO;
            int gx = x0 + c - HALO;
            float v1 = 0.0f, v2 = 0.0f;
            if ((unsigned)gy < (unsigned)IMG && (unsigned)gx < (unsigned)IMG) {
                int o = gy * IMG + gx;
                v1 = p1[o];
                v2 = p2[o];
            }
            s12[r][c] = pk2(v1, v2);
        }
    }
    __syncthreads();

    // hoist weights into registers (uniform across threads)
    u64 G[11];
    #pragma unroll
    for (int k = 0; k < 11; k++) G[k] = ggp[k];

    // ---- horizontal pass: 42 rows x 8 groups of 4 cols = 336 items ----
    for (int it = tid; it < RY * 8; it += 256) {
        int r  = it >> 3;
        int c0 = (it & 7) * 4;
        u64 x[14];
        const ulonglong2* p = (const ulonglong2*)&s12[r][c0];
        #pragma unroll
        for (int i = 0; i < 7; i++) {
            ulonglong2 q = p[i];
            x[2 * i]     = q.x;
            x[2 * i + 1] = q.y;
        }
        #pragma unroll
        for (int j = 0; j < 4; j++) {
            u64 aM = 0, aE = 0;       // bit pattern 0 == (0.f, 0.f)
            float a12 = 0.0f;
            #pragma unroll
            for (int k = 0; k < 11; k++) {
                u64 v = x[j + k];
                u64 t = mul2(G[k], v);          // (g*v1, g*v2)
                aM = add2(aM, t);
                aE = fma2(t, v, aE);            // (g*v1^2, g*v2^2)
                float tlo, thi, v1, v2;
                unpk(t, tlo, thi);
                unpk(v, v1, v2);
                a12 = fmaf(tlo, v2, a12);       // g*v1*v2
            }
            hbM[r][c0 + j]  = aM;
            hbE[r][c0 + j]  = aE;
            hb12[r][c0 + j] = a12;
        }
    }
    __syncthreads();

    // ---- vertical pass: each thread does 4 rows of one column ----
    const int x  = tid & 31;
    const int yb = (tid >> 5) * 4;

    u64 accM[4] = {0, 0, 0, 0};
    u64 accE[4] = {0, 0, 0, 0};
    float acc12[4] = {0.f, 0.f, 0.f, 0.f};

    {
        u64 rowv[14];
        #pragma unroll
        for (int i = 0; i < 14; i++) rowv[i] = hbM[yb + i][x];
        #pragma unroll
        for (int j = 0; j < 4; j++)
            #pragma unroll
            for (int k = 0; k < 11; k++)
                accM[j] = fma2(G[k], rowv[j + k], accM[j]);

        #pragma unroll
        for (int i = 0; i < 14; i++) rowv[i] = hbE[yb + i][x];
        #pragma unroll
        for (int j = 0; j < 4; j++)
            #pragma unroll
            for (int k = 0; k < 11; k++)
                accE[j] = fma2(G[k], rowv[j + k], accE[j]);
    }
    {
        float rows[14];
        #pragma unroll
        for (int i = 0; i < 14; i++) rows[i] = hb12[yb + i][x];
        #pragma unroll
        for (int j = 0; j < 4; j++)
            #pragma unroll
            for (int k = 0; k < 11; k++) {
                float glo, ghi;
                unpk(G[k], glo, ghi);
                acc12[j] = fmaf(glo, rows[j + k], acc12[j]);
            }
    }

    // ---- SSIM epilogue ----
    const float C1 = 1e-4f;
    const float C2 = 9e-4f;
    float lsum = 0.0f;
    #pragma unroll
    for (int j = 0; j < 4; j++) {
        float m1, m2, e11, e22;
        unpk(accM[j], m1, m2);
        unpk(accE[j], e11, e22);
        float m1s = m1 * m1;
        float m2s = m2 * m2;
        float m12 = m1 * m2;
        float num = (2.0f * m12 + C1) * (2.0f * (acc12[j] - m12) + C2);
        float den = (m1s + m2s + C1) * ((e11 - m1s) + (e22 - m2s) + C2);
        lsum += __fdividef(num, den);
    }

    // ---- block reduction ----
    #pragma unroll
    for (int o = 16; o > 0; o >>= 1)
        lsum += __shfl_down_sync(0xffffffffu, lsum, o);
    if ((tid & 31) == 0) warpsum[tid >> 5] = lsum;
    __syncthreads();
    if (tid == 0) {
        float t = 0.f;
        #pragma unroll
        for (int i = 0; i < 8; i++) t += warpsum[i];
        atomicAdd(&g_accum, (double)t);
    }
}

__global__ void ssim_finalize_kernel(float* out) {
    out[0] = (float)(-g_accum / NPIX);
}

extern "C" void kernel_launch(void* const* d_in, const int* in_sizes, int n_in,
                              void* d_out, int out_size)
{
    const float* im1 = (const float*)d_in[0];
    const float* im2 = (const float*)d_in[1];
    const float* win = (const float*)d_in[2];
    float* out = (float*)d_out;

    ssim_zero_kernel<<<1, 1>>>();
    dim3 grid(IMG / TX, IMG / TY, NPLANES);
    ssim_main_kernel<<<grid, 256>>>(im1, im2, win);
    ssim_finalize_kernel<<<1, 1>>>(out);
}